// round 9
// baseline (speedup 1.0000x reference)
#include <cuda_runtime.h>
#include <math.h>
#include <stdint.h>

#define NN 1024
#define DD 64
#define TI 2

// Scratch (device globals — no allocation allowed in kernel_launch).
__device__ float g_s1[NN];
__device__ float g_ssrc[NN * DD];
__device__ float g_t[NN * DD];

// ---- packed fp32x2 helpers (sm_100a: ADD2 / FFMA2) -------------------------
__device__ __forceinline__ float2 f2_add(float2 a, float2 b) {
    float2 c;
    asm("add.rn.f32x2 %0, %1, %2;"
        : "=l"(*reinterpret_cast<unsigned long long*>(&c))
        : "l"(*reinterpret_cast<const unsigned long long*>(&a)),
          "l"(*reinterpret_cast<const unsigned long long*>(&b)));
    return c;
}
__device__ __forceinline__ float2 f2_fma(float2 a, float2 b, float2 c) {
    float2 d;
    asm("fma.rn.f32x2 %0, %1, %2, %3;"
        : "=l"(*reinterpret_cast<unsigned long long*>(&d))
        : "l"(*reinterpret_cast<const unsigned long long*>(&a)),
          "l"(*reinterpret_cast<const unsigned long long*>(&b)),
          "l"(*reinterpret_cast<const unsigned long long*>(&c)));
    return d;
}

// ---------------------------------------------------------------------------
// Kernel A: per-node projections. 256 blocks x 256 threads, 4 nodes/block,
// 2 blocks/SM -> full SM coverage. (proven in R8)
// ---------------------------------------------------------------------------
__global__ __launch_bounds__(256, 2) void gat_pre_kernel(
    const float* __restrict__ x,
    const float* __restrict__ f_w,   // [DD][2*DD] row-major
    const float* __restrict__ f_b,   // [DD]
    const float* __restrict__ w_w)   // [1][2*DD]
{
    __shared__ float fw_sh[128 * 65]; // fw_sh[k*65+d] = f_w[d*128 + k]
    __shared__ float xs[4][DD];
    __shared__ float w1_sh[DD];
    __shared__ float sred[4][2];

    const int tid   = threadIdx.x;
    const int node0 = blockIdx.x * 4;

    for (int i = tid; i < DD * 128; i += 256)
        fw_sh[(i & 127) * 65 + (i >> 7)] = f_w[i];   // conflict-free
    if (tid < DD) w1_sh[tid] = w_w[tid];
    if (tid < 4 * DD) xs[tid >> 6][tid & 63] = x[node0 * DD + tid];
    __syncthreads();

    const int ln   = tid >> 6;   // local node 0..3
    const int d    = tid & 63;
    const int node = node0 + ln;

    float a1 = 0.f, a2 = 0.f;
#pragma unroll
    for (int k = 0; k < DD; ++k) {
        float xa = xs[ln][k];
        a1 = fmaf(xa, fw_sh[k * 65 + d], a1);
        a2 = fmaf(xa, fw_sh[(DD + k) * 65 + d], a2);
    }
    g_ssrc[node * DD + d] = a1;
    g_t[node * DD + d]    = a2 + f_b[d];

    float p = xs[ln][d] * w1_sh[d];
#pragma unroll
    for (int off = 16; off > 0; off >>= 1)
        p += __shfl_down_sync(0xffffffffu, p, off);
    if ((tid & 31) == 0) sred[ln][(tid >> 5) & 1] = p;
    __syncthreads();
    if (d == 0) g_s1[node] = sred[ln][0] + sred[ln][1];
}

// ---------------------------------------------------------------------------
// Kernel B: masked softmax + weighted-relu contraction.
// 512 blocks (TI=2 rows) x 512 threads, 3 CTAs/SM (12 warps/SMSP).
// Half-warp j-split: one warp-wide LDG.128 covers two s_src rows; each
// half-warp computes both output rows for its j. Per iter: 1 LDG + 1 LDS
// + 16 arith. launch_bounds(512,3) caps regs at 42.
// ---------------------------------------------------------------------------
__global__ __launch_bounds__(512, 3) void gat_main_kernel(
    const int* __restrict__ adj,
    float* __restrict__ out)
{
    __shared__ float2 att2[NN * TI];   // att2[j*2+r] = {e,e}  (16 KB)
    __shared__ float  s1_sh[NN];       // 4 KB
    __shared__ float  t_sh[TI * DD];   // 512 B
    __shared__ float  wsum[16 * TI];
    __shared__ float  rowinv[TI];
    __shared__ float  st2[4 * TI * DD];  // stage-2 epilogue partials (2 KB)

    const int tid  = threadIdx.x;
    const int row0 = blockIdx.x * TI;
    const int wid  = tid >> 5;
    const int lane = tid & 31;

    for (int i = tid; i < NN; i += 512) s1_sh[i] = g_s1[i];
    if (tid < TI * DD) t_sh[tid] = g_t[row0 * DD + tid];
    __syncthreads();

    // --- softmax numerators: e[j][r] = adj[r][j]>0 ? exp(s1[j]) : 0 ---------
    {
        float ls[TI] = {0.f, 0.f};
#pragma unroll
        for (int k = 0; k < 2; ++k) {
            int j = wid * 64 + k * 32 + lane;
            float ev = __expf(s1_sh[j]);
#pragma unroll
            for (int rr = 0; rr < TI; ++rr) {
                int a = adj[(row0 + rr) * NN + j];          // coalesced
                float e = (a > 0) ? ev : 0.f;
                att2[j * TI + rr] = make_float2(e, e);
                ls[rr] += e;
            }
        }
#pragma unroll
        for (int rr = 0; rr < TI; ++rr) {
            float v = ls[rr];
#pragma unroll
            for (int off = 16; off > 0; off >>= 1)
                v += __shfl_xor_sync(0xffffffffu, v, off);
            if (lane == 0) wsum[wid * TI + rr] = v;
        }
    }
    __syncthreads();
    if (tid < TI) {
        float s = 0.f;
#pragma unroll
        for (int g = 0; g < 16; ++g) s += wsum[g * TI + tid];
        rowinv[tid] = 1.f / s;
    }

    // --- contraction: acc[r] += e[j][r] * relu(s_src[j] + t[r]) -------------
    const int h  = lane >> 4;        // j parity handled by this half-warp
    const int q  = lane & 15;        // d quad: d = 4q..4q+3
    const int jg = wid;              // j group: [jg*64, (jg+1)*64)

    float2 t2[TI][2];
#pragma unroll
    for (int rr = 0; rr < TI; ++rr)
#pragma unroll
        for (int p = 0; p < 2; ++p)
            t2[rr][p] = *reinterpret_cast<const float2*>(
                &t_sh[rr * DD + 4 * q + 2 * p]);

    float2 acc[TI][2];
#pragma unroll
    for (int rr = 0; rr < TI; ++rr)
        acc[rr][0] = acc[rr][1] = make_float2(0.f, 0.f);

    // lane address: row (2*jj + h), quad q  -> one 512B warp-wide LDG.128
    const float4* __restrict__ sp4 =
        reinterpret_cast<const float4*>(g_ssrc + (jg * 64 + h) * DD) + q;
    // 16 B of dup e per j row: {e0,e0,e1,e1}
    const float4* __restrict__ ap4 =
        reinterpret_cast<const float4*>(att2) + jg * 64 + h;

#pragma unroll 8
    for (int jj = 0; jj < 32; ++jj) {
        float4 s4 = sp4[jj * 32];            // rows 2jj & 2jj+1 in one LDG
        float4 eA = ap4[jj * 2];             // {e0,e0,e1,e1} for own row
        float2 sa = make_float2(s4.x, s4.y);
        float2 sb = make_float2(s4.z, s4.w);

#define GAT_STEP(RR, EPAIR)                                  \
        {                                                    \
            float2 ua = f2_add(sa, t2[RR][0]);               \
            float2 ub = f2_add(sb, t2[RR][1]);               \
            ua.x = fmaxf(ua.x, 0.f);  ua.y = fmaxf(ua.y, 0.f); \
            ub.x = fmaxf(ub.x, 0.f);  ub.y = fmaxf(ub.y, 0.f); \
            acc[RR][0] = f2_fma((EPAIR), ua, acc[RR][0]);    \
            acc[RR][1] = f2_fma((EPAIR), ub, acc[RR][1]);    \
        }
        GAT_STEP(0, make_float2(eA.x, eA.y))
        GAT_STEP(1, make_float2(eA.z, eA.w))
#undef GAT_STEP
    }

    // --- epilogue: reduce 32 half-warp partials (two stages), store ---------
    __syncthreads();                       // everyone done reading att2
    float* part = reinterpret_cast<float*>(att2);   // reuse: [32][TI][DD] 16KB
#pragma unroll
    for (int rr = 0; rr < TI; ++rr) {
        float4 v = make_float4(acc[rr][0].x, acc[rr][0].y,
                               acc[rr][1].x, acc[rr][1].y);
        *reinterpret_cast<float4*>(
            &part[((jg * 2 + h) * TI + rr) * DD + 4 * q]) = v;
    }
    __syncthreads();

    {   // stage 1: 512 threads, each sums 8 of 32 groups for one (rr,d)
        int g8 = tid >> 7;          // 0..3
        int rr = (tid >> 6) & 1;
        int d  = tid & 63;
        float s = 0.f;
#pragma unroll
        for (int g = 0; g < 8; ++g)
            s += part[((g8 * 8 + g) * TI + rr) * DD + d];
        st2[(g8 * TI + rr) * DD + d] = s;
    }
    __syncthreads();
    if (tid < TI * DD) {            // stage 2: 128 threads, sum 4 + store
        int rr = tid >> 6;
        int d  = tid & 63;
        float s = 0.f;
#pragma unroll
        for (int g = 0; g < 4; ++g)
            s += st2[(g * TI + rr) * DD + d];
        out[(row0 + rr) * DD + d] = s * rowinv[rr];
    }
}

// ---------------------------------------------------------------------------
// Inputs (metadata order): 0 x[1024,64] f32, 1 adj[1024,1024] i32,
// 2 src i64 (unused), 3 tgt i64 (unused), 4 Msrc (unused), 5 Mtgt (unused),
// 6 f_w[64,128] f32, 7 f_b[64] f32, 8 w_w[1,128] f32, 9 w_b[1] f32 (cancels).
// Output: o[1024,64] f32.
// ---------------------------------------------------------------------------
extern "C" void kernel_launch(void* const* d_in, const int* in_sizes, int n_in,
                              void* d_out, int out_size)
{
    const float* x   = (const float*)d_in[0];
    const int*   adj = (const int*)d_in[1];
    const float* f_w = (const float*)d_in[6];
    const float* f_b = (const float*)d_in[7];
    const float* w_w = (const float*)d_in[8];
    float* out = (float*)d_out;

    gat_pre_kernel<<<256, 256>>>(x, f_w, f_b, w_w);
    gat_main_kernel<<<NN / TI, 512>>>(adj, out);
}

// round 10
// speedup vs baseline: 1.1874x; 1.1874x over previous
#include <cuda_runtime.h>
#include <math.h>
#include <stdint.h>

#define NN 1024
#define DD 64
#define TI 4

// Scratch (device globals — no allocation allowed in kernel_launch).
// g_ssrc padded 16 rows: prefetch lookahead (distance 4 iters = 8 rows) never
// touches unmapped memory.
__device__ float g_s1[NN];
__device__ float g_ssrc[(NN + 16) * DD];
__device__ float g_t[NN * DD];

// ---- packed fp32x2 helpers (sm_100a: ADD2 / FFMA2) -------------------------
__device__ __forceinline__ float2 f2_add(float2 a, float2 b) {
    float2 c;
    asm("add.rn.f32x2 %0, %1, %2;"
        : "=l"(*reinterpret_cast<unsigned long long*>(&c))
        : "l"(*reinterpret_cast<const unsigned long long*>(&a)),
          "l"(*reinterpret_cast<const unsigned long long*>(&b)));
    return c;
}
__device__ __forceinline__ float2 f2_fma(float2 a, float2 b, float2 c) {
    float2 d;
    asm("fma.rn.f32x2 %0, %1, %2, %3;"
        : "=l"(*reinterpret_cast<unsigned long long*>(&d))
        : "l"(*reinterpret_cast<const unsigned long long*>(&a)),
          "l"(*reinterpret_cast<const unsigned long long*>(&b)),
          "l"(*reinterpret_cast<const unsigned long long*>(&c)));
    return d;
}

// ---------------------------------------------------------------------------
// Kernel A: per-node projections. 256 blocks x 256 threads, 4 nodes/block,
// 2 blocks/SM -> full SM coverage. (proven in R8)
// ---------------------------------------------------------------------------
__global__ __launch_bounds__(256, 2) void gat_pre_kernel(
    const float* __restrict__ x,
    const float* __restrict__ f_w,   // [DD][2*DD] row-major
    const float* __restrict__ f_b,   // [DD]
    const float* __restrict__ w_w)   // [1][2*DD]
{
    __shared__ float fw_sh[128 * 65]; // fw_sh[k*65+d] = f_w[d*128 + k]
    __shared__ float xs[4][DD];
    __shared__ float w1_sh[DD];
    __shared__ float sred[4][2];

    const int tid   = threadIdx.x;
    const int node0 = blockIdx.x * 4;

    for (int i = tid; i < DD * 128; i += 256)
        fw_sh[(i & 127) * 65 + (i >> 7)] = f_w[i];   // conflict-free
    if (tid < DD) w1_sh[tid] = w_w[tid];
    if (tid < 4 * DD) xs[tid >> 6][tid & 63] = x[node0 * DD + tid];
    __syncthreads();

    const int ln   = tid >> 6;   // local node 0..3
    const int d    = tid & 63;
    const int node = node0 + ln;

    float a1 = 0.f, a2 = 0.f;
#pragma unroll
    for (int k = 0; k < DD; ++k) {
        float xa = xs[ln][k];
        a1 = fmaf(xa, fw_sh[k * 65 + d], a1);
        a2 = fmaf(xa, fw_sh[(DD + k) * 65 + d], a2);
    }
    g_ssrc[node * DD + d] = a1;
    g_t[node * DD + d]    = a2 + f_b[d];

    float p = xs[ln][d] * w1_sh[d];
#pragma unroll
    for (int off = 16; off > 0; off >>= 1)
        p += __shfl_down_sync(0xffffffffu, p, off);
    if ((tid & 31) == 0) sred[ln][(tid >> 5) & 1] = p;
    __syncthreads();
    if (d == 0) g_s1[node] = sred[ln][0] + sred[ln][1];
}

// ---------------------------------------------------------------------------
// Kernel B: masked softmax + weighted-relu contraction.
// 256 blocks (TI=4 rows) x 512 threads, 2 CTAs/SM. (R8 layout.)
// Main loop: one warp-wide LDG.128 covers TWO s_src rows; each half-warp
// computes all 4 output rows for its j. NEW: per-iter prefetch.global.L1 at
// distance 4 iterations turns the L2-latency-exposed LDG into an L1 hit —
// pipeline depth without registers.
// ---------------------------------------------------------------------------
__global__ __launch_bounds__(512, 2) void gat_main_kernel(
    const int* __restrict__ adj,
    float* __restrict__ out)
{
    __shared__ float2 att2[NN * TI];   // att2[j*4+r] = {e,e}  (32 KB)
    __shared__ float  s1_sh[NN];       // 4 KB
    __shared__ float  t_sh[TI * DD];   // 1 KB
    __shared__ float  wsum[16 * TI];
    __shared__ float  rowinv[TI];

    const int tid  = threadIdx.x;
    const int row0 = blockIdx.x * TI;
    const int wid  = tid >> 5;
    const int lane = tid & 31;

    for (int i = tid; i < NN; i += 512) s1_sh[i] = g_s1[i];
    if (tid < TI * DD) t_sh[tid] = g_t[row0 * DD + tid];
    __syncthreads();

    // --- softmax numerators: e[j][r] = adj[r][j]>0 ? exp(s1[j]) : 0 ---------
    {
        float ls[TI] = {0.f, 0.f, 0.f, 0.f};
#pragma unroll
        for (int k = 0; k < 2; ++k) {
            int j = wid * 64 + k * 32 + lane;
            float ev = __expf(s1_sh[j]);
#pragma unroll
            for (int rr = 0; rr < TI; ++rr) {
                int a = adj[(row0 + rr) * NN + j];          // coalesced
                float e = (a > 0) ? ev : 0.f;
                att2[j * TI + rr] = make_float2(e, e);
                ls[rr] += e;
            }
        }
#pragma unroll
        for (int rr = 0; rr < TI; ++rr) {
            float v = ls[rr];
#pragma unroll
            for (int off = 16; off > 0; off >>= 1)
                v += __shfl_xor_sync(0xffffffffu, v, off);
            if (lane == 0) wsum[wid * TI + rr] = v;
        }
    }
    __syncthreads();
    if (tid < TI) {
        float s = 0.f;
#pragma unroll
        for (int g = 0; g < 16; ++g) s += wsum[g * TI + tid];
        rowinv[tid] = 1.f / s;
    }

    // --- contraction: acc[r] += e[j][r] * relu(s_src[j] + t[r]) -------------
    const int h = lane >> 4;         // j parity handled by this half-warp
    const int q = lane & 15;         // d quad: d = 4q..4q+3
    const int jg = wid;              // j group: [jg*64, (jg+1)*64)

    float2 t2[TI][2];
#pragma unroll
    for (int rr = 0; rr < TI; ++rr)
#pragma unroll
        for (int p = 0; p < 2; ++p)
            t2[rr][p] = *reinterpret_cast<const float2*>(
                &t_sh[rr * DD + 4 * q + 2 * p]);

    float2 acc[TI][2];
#pragma unroll
    for (int rr = 0; rr < TI; ++rr)
        acc[rr][0] = acc[rr][1] = make_float2(0.f, 0.f);

    // lane address: row (2*jj + h), quad q  -> one 512B warp-wide LDG.128
    const float4* __restrict__ sp4 =
        reinterpret_cast<const float4*>(g_ssrc + (jg * 64 + h) * DD) + q;
    const float4* __restrict__ ap4 =
        reinterpret_cast<const float4*>(att2 + (jg * 64 + h) * TI);

    // Warm the L1 for the first 4 iterations.
#pragma unroll
    for (int w = 0; w < 4; ++w)
        asm volatile("prefetch.global.L1 [%0];" :: "l"(sp4 + w * 32));

#pragma unroll 8
    for (int jj = 0; jj < 32; ++jj) {
        // Distance-4 lookahead: line arrives from L2 long before its LDG.
        asm volatile("prefetch.global.L1 [%0];" :: "l"(sp4 + (jj + 4) * 32));

        float4 s4 = sp4[jj * 32];            // rows 2jj & 2jj+1 in one LDG
        float4 eA = ap4[jj * 4];             // {e0,e0,e1,e1} (bcast per half)
        float4 eB = ap4[jj * 4 + 1];         // {e2,e2,e3,e3}
        float2 sa = make_float2(s4.x, s4.y);
        float2 sb = make_float2(s4.z, s4.w);

#define GAT_STEP(RR, EPAIR)                                  \
        {                                                    \
            float2 ua = f2_add(sa, t2[RR][0]);               \
            float2 ub = f2_add(sb, t2[RR][1]);               \
            ua.x = fmaxf(ua.x, 0.f);  ua.y = fmaxf(ua.y, 0.f); \
            ub.x = fmaxf(ub.x, 0.f);  ub.y = fmaxf(ub.y, 0.f); \
            acc[RR][0] = f2_fma((EPAIR), ua, acc[RR][0]);    \
            acc[RR][1] = f2_fma((EPAIR), ub, acc[RR][1]);    \
        }
        GAT_STEP(0, make_float2(eA.x, eA.y))
        GAT_STEP(1, make_float2(eA.z, eA.w))
        GAT_STEP(2, make_float2(eB.x, eB.y))
        GAT_STEP(3, make_float2(eB.z, eB.w))
#undef GAT_STEP
    }

    // --- epilogue: reduce 32 half-warp partials, normalize, store -----------
    __syncthreads();                       // everyone done reading att2
    float* part = reinterpret_cast<float*>(att2);   // reuse: [32][TI][DD]
#pragma unroll
    for (int rr = 0; rr < TI; ++rr) {
        float4 v = make_float4(acc[rr][0].x, acc[rr][0].y,
                               acc[rr][1].x, acc[rr][1].y);
        *reinterpret_cast<float4*>(
            &part[((jg * 2 + h) * TI + rr) * DD + 4 * q]) = v;
    }
    __syncthreads();

    if (tid < TI * DD) {                   // 256 threads: (rr, d)
        int rr = tid >> 6;
        int d  = tid & 63;
        float s = 0.f;
#pragma unroll
        for (int g = 0; g < 32; ++g)
            s += part[(g * TI + rr) * DD + d];
        out[(row0 + rr) * DD + d] = s * rowinv[rr];
    }
}

// ---------------------------------------------------------------------------
// Inputs (metadata order): 0 x[1024,64] f32, 1 adj[1024,1024] i32,
// 2 src i64 (unused), 3 tgt i64 (unused), 4 Msrc (unused), 5 Mtgt (unused),
// 6 f_w[64,128] f32, 7 f_b[64] f32, 8 w_w[1,128] f32, 9 w_b[1] f32 (cancels).
// Output: o[1024,64] f32.
// ---------------------------------------------------------------------------
extern "C" void kernel_launch(void* const* d_in, const int* in_sizes, int n_in,
                              void* d_out, int out_size)
{
    const float* x   = (const float*)d_in[0];
    const int*   adj = (const int*)d_in[1];
    const float* f_w = (const float*)d_in[6];
    const float* f_b = (const float*)d_in[7];
    const float* w_w = (const float*)d_in[8];
    float* out = (float*)d_out;

    gat_pre_kernel<<<256, 256>>>(x, f_w, f_b, w_w);
    gat_main_kernel<<<NN / TI, 512>>>(adj, out);
}

// round 12
// speedup vs baseline: 1.2059x; 1.0156x over previous
#include <cuda_runtime.h>
#include <math.h>
#include <stdint.h>

#define NN 1024
#define DD 64
#define TI 4

// Scratch (device globals — no allocation allowed in kernel_launch).
__device__ float g_s1[NN];
__device__ float g_ssrc[NN * DD];
__device__ float g_t[NN * DD];

// ---- packed fp32x2 helpers (sm_100a: ADD2 / FFMA2) -------------------------
__device__ __forceinline__ float2 f2_add(float2 a, float2 b) {
    float2 c;
    asm("add.rn.f32x2 %0, %1, %2;"
        : "=l"(*reinterpret_cast<unsigned long long*>(&c))
        : "l"(*reinterpret_cast<const unsigned long long*>(&a)),
          "l"(*reinterpret_cast<const unsigned long long*>(&b)));
    return c;
}
__device__ __forceinline__ float2 f2_fma(float2 a, float2 b, float2 c) {
    float2 d;
    asm("fma.rn.f32x2 %0, %1, %2, %3;"
        : "=l"(*reinterpret_cast<unsigned long long*>(&d))
        : "l"(*reinterpret_cast<const unsigned long long*>(&a)),
          "l"(*reinterpret_cast<const unsigned long long*>(&b)),
          "l"(*reinterpret_cast<const unsigned long long*>(&c)));
    return d;
}

// ---------------------------------------------------------------------------
// Kernel A: per-node projections. 256 blocks x 256 threads, 4 nodes/block,
// 2 blocks/SM -> full SM coverage. (proven in R8)
// ---------------------------------------------------------------------------
__global__ __launch_bounds__(256, 2) void gat_pre_kernel(
    const float* __restrict__ x,
    const float* __restrict__ f_w,   // [DD][2*DD] row-major
    const float* __restrict__ f_b,   // [DD]
    const float* __restrict__ w_w)   // [1][2*DD]
{
    __shared__ float fw_sh[128 * 65]; // fw_sh[k*65+d] = f_w[d*128 + k]
    __shared__ float xs[4][DD];
    __shared__ float w1_sh[DD];
    __shared__ float sred[4][2];

    const int tid   = threadIdx.x;
    const int node0 = blockIdx.x * 4;

    for (int i = tid; i < DD * 128; i += 256)
        fw_sh[(i & 127) * 65 + (i >> 7)] = f_w[i];   // conflict-free
    if (tid < DD) w1_sh[tid] = w_w[tid];
    if (tid < 4 * DD) xs[tid >> 6][tid & 63] = x[node0 * DD + tid];
    __syncthreads();

    const int ln   = tid >> 6;   // local node 0..3
    const int d    = tid & 63;
    const int node = node0 + ln;

    float a1 = 0.f, a2 = 0.f;
#pragma unroll
    for (int k = 0; k < DD; ++k) {
        float xa = xs[ln][k];
        a1 = fmaf(xa, fw_sh[k * 65 + d], a1);
        a2 = fmaf(xa, fw_sh[(DD + k) * 65 + d], a2);
    }
    g_ssrc[node * DD + d] = a1;
    g_t[node * DD + d]    = a2 + f_b[d];

    float p = xs[ln][d] * w1_sh[d];
#pragma unroll
    for (int off = 16; off > 0; off >>= 1)
        p += __shfl_down_sync(0xffffffffu, p, off);
    if ((tid & 31) == 0) sred[ln][(tid >> 5) & 1] = p;
    __syncthreads();
    if (d == 0) g_s1[node] = sred[ln][0] + sred[ln][1];
}

// ---------------------------------------------------------------------------
// Kernel B: masked softmax + weighted-relu contraction (R8 main loop).
// 256 blocks (TI=4 rows) x 512 threads, 2 CTAs/SM, ~57 KB DYNAMIC smem.
// PDL: stages its 16 KB of adj into smem (independent of the pre-kernel)
// BEFORE cudaGridDependencySynchronize(), overlapping pre-kernel + ramp.
// ---------------------------------------------------------------------------
#define SM_ATT   0                        // float2 att2[NN*TI]    32768 B
#define SM_ADJ   32768                    // int adj_sh[TI*NN]     16384 B
#define SM_S1    49152                    // float s1_sh[NN]        4096 B
#define SM_T     53248                    // float t_sh[TI*DD]      1024 B
#define SM_WSUM  54272                    // float wsum[16*TI]       256 B
#define SM_RINV  54528                    // float rowinv[TI]         64 B
#define SM_ST2   54592                    // float st2[2*TI*DD]     2048 B
#define SM_SIZE  56640

__global__ __launch_bounds__(512, 2) void gat_main_kernel(
    const int* __restrict__ adj,
    float* __restrict__ out)
{
    extern __shared__ __align__(16) char dsm[];
    float2* att2   = reinterpret_cast<float2*>(dsm + SM_ATT);
    int*    adj_sh = reinterpret_cast<int*>(dsm + SM_ADJ);
    float*  s1_sh  = reinterpret_cast<float*>(dsm + SM_S1);
    float*  t_sh   = reinterpret_cast<float*>(dsm + SM_T);
    float*  wsum   = reinterpret_cast<float*>(dsm + SM_WSUM);
    float*  rowinv = reinterpret_cast<float*>(dsm + SM_RINV);
    float*  st2    = reinterpret_cast<float*>(dsm + SM_ST2);

    const int tid  = threadIdx.x;
    const int row0 = blockIdx.x * TI;
    const int wid  = tid >> 5;
    const int lane = tid & 31;

    // --- Overlap region: adj staging needs nothing from the pre-kernel ------
    {
        const int4* __restrict__ asrc =
            reinterpret_cast<const int4*>(adj + row0 * NN);
        int4* __restrict__ adst = reinterpret_cast<int4*>(adj_sh);
#pragma unroll
        for (int i = 0; i < 2; ++i)
            adst[tid + i * 512] = asrc[tid + i * 512];   // 16 KB coalesced
    }
    cudaGridDependencySynchronize();    // pre-kernel results now visible

    for (int i = tid; i < NN; i += 512) s1_sh[i] = g_s1[i];
    if (tid < TI * DD) t_sh[tid] = g_t[row0 * DD + tid];
    __syncthreads();

    // --- softmax numerators: e[j][r] = adj[r][j]>0 ? exp(s1[j]) : 0 ---------
    {
        float ls[TI] = {0.f, 0.f, 0.f, 0.f};
#pragma unroll
        for (int k = 0; k < 2; ++k) {
            int j = wid * 64 + k * 32 + lane;
            float ev = __expf(s1_sh[j]);
#pragma unroll
            for (int rr = 0; rr < TI; ++rr) {
                int a = adj_sh[rr * NN + j];             // from smem
                float e = (a > 0) ? ev : 0.f;
                att2[j * TI + rr] = make_float2(e, e);
                ls[rr] += e;
            }
        }
#pragma unroll
        for (int rr = 0; rr < TI; ++rr) {
            float v = ls[rr];
#pragma unroll
            for (int off = 16; off > 0; off >>= 1)
                v += __shfl_xor_sync(0xffffffffu, v, off);
            if (lane == 0) wsum[wid * TI + rr] = v;
        }
    }
    __syncthreads();
    if (tid < TI) {
        float s = 0.f;
#pragma unroll
        for (int g = 0; g < 16; ++g) s += wsum[g * TI + tid];
        rowinv[tid] = 1.f / s;
    }

    // --- contraction: acc[r] += e[j][r] * relu(s_src[j] + t[r]) -------------
    const int h = lane >> 4;         // j parity handled by this half-warp
    const int q = lane & 15;         // d quad: d = 4q..4q+3
    const int jg = wid;              // j group: [jg*64, (jg+1)*64)

    float2 t2[TI][2];
#pragma unroll
    for (int rr = 0; rr < TI; ++rr)
#pragma unroll
        for (int p = 0; p < 2; ++p)
            t2[rr][p] = *reinterpret_cast<const float2*>(
                &t_sh[rr * DD + 4 * q + 2 * p]);

    float2 acc[TI][2];
#pragma unroll
    for (int rr = 0; rr < TI; ++rr)
        acc[rr][0] = acc[rr][1] = make_float2(0.f, 0.f);

    // lane address: row (2*jj + h), quad q  -> one 512B warp-wide LDG.128
    const float4* __restrict__ sp4 =
        reinterpret_cast<const float4*>(g_ssrc + (jg * 64 + h) * DD) + q;
    const float4* __restrict__ ap4 =
        reinterpret_cast<const float4*>(att2 + (jg * 64 + h) * TI);

#pragma unroll 8
    for (int jj = 0; jj < 32; ++jj) {
        float4 s4 = sp4[jj * 32];            // rows 2jj & 2jj+1 in one LDG
        float4 eA = ap4[jj * 4];             // {e0,e0,e1,e1} (bcast per half)
        float4 eB = ap4[jj * 4 + 1];         // {e2,e2,e3,e3}
        float2 sa = make_float2(s4.x, s4.y);
        float2 sb = make_float2(s4.z, s4.w);

#define GAT_STEP(RR, EPAIR)                                  \
        {                                                    \
            float2 ua = f2_add(sa, t2[RR][0]);               \
            float2 ub = f2_add(sb, t2[RR][1]);               \
            ua.x = fmaxf(ua.x, 0.f);  ua.y = fmaxf(ua.y, 0.f); \
            ub.x = fmaxf(ub.x, 0.f);  ub.y = fmaxf(ub.y, 0.f); \
            acc[RR][0] = f2_fma((EPAIR), ua, acc[RR][0]);    \
            acc[RR][1] = f2_fma((EPAIR), ub, acc[RR][1]);    \
        }
        GAT_STEP(0, make_float2(eA.x, eA.y))
        GAT_STEP(1, make_float2(eA.z, eA.w))
        GAT_STEP(2, make_float2(eB.x, eB.y))
        GAT_STEP(3, make_float2(eB.z, eB.w))
#undef GAT_STEP
    }

    // --- epilogue: reduce 32 half-warp partials (two stages), store ---------
    __syncthreads();                       // everyone done reading att2
    float* part = reinterpret_cast<float*>(att2);   // reuse: [32][TI][DD]
#pragma unroll
    for (int rr = 0; rr < TI; ++rr) {
        float4 v = make_float4(acc[rr][0].x, acc[rr][0].y,
                               acc[rr][1].x, acc[rr][1].y);
        *reinterpret_cast<float4*>(
            &part[((jg * 2 + h) * TI + rr) * DD + 4 * q]) = v;
    }
    __syncthreads();

    {   // stage 1: 512 threads = (g2, rr, d); each sums 16 of 32 groups
        int g2 = tid >> 8;          // 0..1
        int rr = (tid >> 6) & 3;
        int d  = tid & 63;
        float s = 0.f;
#pragma unroll
        for (int g = 0; g < 16; ++g)
            s += part[((g2 * 16 + g) * TI + rr) * DD + d];
        st2[(g2 * TI + rr) * DD + d] = s;
    }
    __syncthreads();
    if (tid < TI * DD) {            // stage 2: 256 threads, sum 2 + store
        int rr = tid >> 6;
        int d  = tid & 63;
        float s = st2[rr * DD + d] + st2[(TI + rr) * DD + d];
        out[(row0 + rr) * DD + d] = s * rowinv[rr];
    }
}

// ---------------------------------------------------------------------------
// Inputs (metadata order): 0 x[1024,64] f32, 1 adj[1024,1024] i32,
// 2 src i64 (unused), 3 tgt i64 (unused), 4 Msrc (unused), 5 Mtgt (unused),
// 6 f_w[64,128] f32, 7 f_b[64] f32, 8 w_w[1,128] f32, 9 w_b[1] f32 (cancels).
// Output: o[1024,64] f32.
// ---------------------------------------------------------------------------
extern "C" void kernel_launch(void* const* d_in, const int* in_sizes, int n_in,
                              void* d_out, int out_size)
{
    const float* x   = (const float*)d_in[0];
    const int*   adj = (const int*)d_in[1];
    const float* f_w = (const float*)d_in[6];
    const float* f_b = (const float*)d_in[7];
    const float* w_w = (const float*)d_in[8];

    cudaFuncSetAttribute(gat_main_kernel,
                         cudaFuncAttributeMaxDynamicSharedMemorySize,
                         SM_SIZE);

    gat_pre_kernel<<<256, 256>>>(x, f_w, f_b, w_w);

    // Main kernel with Programmatic Dependent Launch: overlaps its adj
    // staging with the tail of the pre-kernel.
    cudaLaunchConfig_t cfg = {};
    cfg.gridDim  = dim3(NN / TI);
    cfg.blockDim = dim3(512);
    cfg.dynamicSmemBytes = SM_SIZE;
    cfg.stream = 0;
    cudaLaunchAttribute attr[1];
    attr[0].id = cudaLaunchAttributeProgrammaticStreamSerialization;
    attr[0].val.programmaticStreamSerializationAllowed = 1;
    cfg.attrs = attr;
    cfg.numAttrs = 1;
    cudaLaunchKernelEx(&cfg, gat_main_kernel, adj, (float*)d_out);
}